// round 11
// baseline (speedup 1.0000x reference)
#include <cuda_runtime.h>
#include <math.h>
#include <stdint.h>

#define BB 32
#define AA 9
#define HH 128
#define WW 128
#define NN (AA*HH*WW)      /* 147456 */
#define NF4 (NN/4)         /* 36864 float4 per image slab */
#define ITER (NF4/1024)    /* 36 */
#define PRE 6000
#define POST 300
#define CAP 8192
#define TGT 7000           /* raw-score cumcount target: >=PRE slack, <=CAP slack */
#define NMS_T 0.7f
#define NBIN 2048
#define FULLM 0xFFFFFFFFu

// Anchors: generate_anchors(16,[.5,1,2],[8,16,32]) — exact integers, verified vs numpy.
__constant__ float c_anch[AA*4] = {
   -84.f, -40.f,  99.f,  55.f,
  -176.f, -88.f, 191.f, 103.f,
  -360.f,-184.f, 375.f, 199.f,
   -56.f, -56.f,  71.f,  71.f,
  -120.f,-120.f, 135.f, 135.f,
  -248.f,-248.f, 263.f, 263.f,
   -36.f, -80.f,  51.f,  95.f,
   -80.f,-168.f,  95.f, 183.f,
  -168.f,-344.f, 183.f, 359.f
};

// Only global scratch: per-image histogram. Zero-initialized at module load;
// k_back re-zeros its slab at the end of every launch, so the "starts zeroed"
// invariant holds across graph replays deterministically.
__device__ unsigned g_hist[BB*NBIN];

__device__ __forceinline__ unsigned keyOf(float f){
    unsigned u = __float_as_uint(f);
    return (u & 0x80000000u) ? ~u : (u | 0x80000000u);
}

__device__ __forceinline__ void decode_box(const float* __restrict__ pred,
                                           int b, int a, int y, int x,
                                           float imh, float imw,
                                           float& x1, float& y1, float& x2, float& y2,
                                           float& ws, float& hs){
    float sx = (float)(x*16), sy = (float)(y*16);
    float a0 = c_anch[a*4+0]+sx, a1 = c_anch[a*4+1]+sy;
    float a2 = c_anch[a*4+2]+sx, a3 = c_anch[a*4+3]+sy;
    float aw = a2-a0+1.0f, ah = a3-a1+1.0f;
    float cx = a0+0.5f*aw,  cy = a1+0.5f*ah;
    int base = ((b*4*AA + 4*a)*HH + y)*WW + x;
    float dx = pred[base];
    float dy = pred[base +   HH*WW];
    float dw = pred[base + 2*HH*WW];
    float dh = pred[base + 3*HH*WW];
    float pcx = dx*aw+cx, pcy = dy*ah+cy;
    float pw = expf(dw)*aw, ph = expf(dh)*ah;
    x1 = pcx-0.5f*pw; y1 = pcy-0.5f*ph; x2 = pcx+0.5f*pw; y2 = pcy+0.5f*ph;
    x1 = fminf(fmaxf(x1,0.0f), imw-1.0f);
    y1 = fminf(fmaxf(y1,0.0f), imh-1.0f);
    x2 = fminf(fmaxf(x2,0.0f), imw-1.0f);
    y2 = fminf(fmaxf(y2,0.0f), imh-1.0f);
    ws = x2-x1+1.0f; hs = y2-y1+1.0f;
}

// key -> bin (monotone). Fine bins (13-bit key granularity) over key >= keyOf(0.5).
__device__ __forceinline__ unsigned binOf(unsigned key){
    if (key >= 0xBF000000u){
        unsigned b = 1024u + ((key - 0xBF000000u) >> 13);
        return b > 2047u ? 2047u : b;
    }
    unsigned b = key >> 22;
    return b > 1023u ? 1023u : b;
}
__device__ __forceinline__ unsigned binStartKey(unsigned t){
    return (t >= 1024u) ? (0xBF000000u + ((t - 1024u) << 13)) : (t << 22);
}

// ---------------- K1: wide raw-score histogram (cls only) ----------------
__global__ void k_hist(const float* __restrict__ cls){
    __shared__ unsigned h[NBIN];
    int b = blockIdx.y, tid = threadIdx.x;
    const float4* sp = (const float4*)(cls + ((size_t)b*2*AA + AA)*HH*WW);
    for (int i=tid;i<NBIN;i+=1024) h[i]=0u;
    __syncthreads();
    #pragma unroll
    for (int i=0;i<2;i++){
        float4 v = sp[(blockIdx.x*2 + i)*1024 + tid];
        atomicAdd(&h[binOf(keyOf(v.x))], 1u);
        atomicAdd(&h[binOf(keyOf(v.y))], 1u);
        atomicAdd(&h[binOf(keyOf(v.z))], 1u);
        atomicAdd(&h[binOf(keyOf(v.w))], 1u);
    }
    __syncthreads();
    for (int i=tid;i<NBIN;i+=1024)
        if (h[i]) atomicAdd(&g_hist[b*NBIN+i], h[i]);
}

// Register/shfl bitonic stage: thread owns 8 contiguous items, all indices static.
template<unsigned J>
__device__ __forceinline__ void reg_stage(unsigned long long r[8], unsigned tid, unsigned k){
    if constexpr (J >= 8u){
        constexpr unsigned lm = J >> 3;
        bool amLow = ((tid & lm) == 0u);
        #pragma unroll
        for (int c=0;c<8;c++){
            unsigned long long other = __shfl_xor_sync(FULLM, r[c], lm);
            bool d = (((tid*8u + (unsigned)c) & k) == 0u);  // desc
            bool takeMax = (d == amLow);
            unsigned long long mx = (r[c] > other) ? r[c] : other;
            unsigned long long mn = (r[c] > other) ? other : r[c];
            r[c] = takeMax ? mx : mn;
        }
    } else {
        #pragma unroll
        for (int c=0;c<8;c++){
            constexpr int JJ = (int)J;
            int p = c ^ JJ;
            if (p > c){
                bool d = (((tid*8u + (unsigned)c) & k) == 0u);
                if ((r[c] < r[p]) == d){
                    unsigned long long t=r[c]; r[c]=r[p]; r[p]=t;
                }
            }
        }
    }
    if constexpr (J > 1u) reg_stage<J/2u>(r, tid, k);
}

// ========== K2: per-image thresh + compact + sort + NMS (fused back end) ==========
__global__ void __launch_bounds__(1024,1)
k_back(const float* __restrict__ cls, const float* __restrict__ pred,
       const float* __restrict__ info, float* __restrict__ out){
    extern __shared__ char smem[];
    unsigned long long* items = (unsigned long long*)smem;        // 64KB
    float4*   boxes = (float4*)(smem + CAP*8);                    // 96KB (after thresh)
    unsigned* h0    = (unsigned*)(smem + CAP*8);                  // overlaps boxes
    unsigned* h1    = h0 + NBIN;

    __shared__ float4   s_kept[POST];
    __shared__ float    s_karea[POST];
    __shared__ float4   s_bc;
    __shared__ int      s_wcnt[32];
    __shared__ unsigned s_warp[32];
    __shared__ unsigned s_K;
    __shared__ int      s_nk;

    int b = blockIdx.x;
    unsigned tid = threadIdx.x;
    int lane = tid & 31, wid = tid >> 5;
    const float4* sp = (const float4*)(cls + ((size_t)b*2*AA + AA)*HH*WW);
    float imh = __ldg(&info[b*3+0]);
    float imw = __ldg(&info[b*3+1]);
    float minsz = 16.0f*__ldg(&info[b*3+2]);

    // ---- Phase T: load hist, suffix scan -> threshold key ----
    for (int i=tid;i<NBIN;i+=1024) h0[i] = g_hist[b*NBIN+i];
    for (int i=tid;i<CAP;i+=1024) items[i] = 0ull;
    __syncthreads();
    unsigned *src=h0, *dst=h1;
    for (int off=1; off<NBIN; off<<=1){
        for (int i=tid;i<NBIN;i+=1024)
            dst[i] = src[i] + ((i+off<NBIN)? src[i+off] : 0u);
        __syncthreads();
        unsigned* t = src; src = dst; dst = t;
    }
    for (int i=tid;i<NBIN;i+=1024){
        unsigned si = src[i];
        unsigned nx = (i+1<NBIN)? src[i+1] : 0u;
        if (si >= TGT && nx < TGT) s_K = binStartKey((unsigned)i);
    }
    __syncthreads();
    unsigned K = s_K;

    // ---- Phase C pass 1: count survivors (L2-warm re-read of cls) ----
    unsigned ok[5] = {0u,0u,0u,0u,0u};
    int cntme = 0;
    #pragma unroll 4
    for (int i=0;i<ITER;i++){
        float4 v = sp[i*1024 + tid];
        unsigned g = 0u;
        if (keyOf(v.x) >= K) g |= 1u;
        if (keyOf(v.y) >= K) g |= 2u;
        if (keyOf(v.z) >= K) g |= 4u;
        if (keyOf(v.w) >= K) g |= 8u;
        ok[i>>3] |= g << ((i&7)*4);
        cntme += __popc(g);
    }
    int wtot = __reduce_add_sync(FULLM, cntme);
    if (lane==0) s_wcnt[wid] = wtot;
    __syncthreads();
    if (wid==0){
        int v = s_wcnt[lane];
        int inc = v;
        #pragma unroll
        for (int o=1;o<32;o<<=1){
            int t = __shfl_up_sync(FULLM, inc, o);
            if (lane >= o) inc += t;
        }
        s_wcnt[lane] = inc - v;   // exclusive warp base
    }
    __syncthreads();
    int base = s_wcnt[wid];

    // ---- Phase C pass 2: decode+filter survivors -> items in smem (no atomics) ----
    for (int i=0;i<ITER;i++){
        unsigned g = (ok[i>>3] >> ((i&7)*4)) & 0xFu;
        unsigned any = __ballot_sync(FULLM, g != 0u);
        if (any){
            float4 v = sp[i*1024 + tid];
            #pragma unroll
            for (int c=0;c<4;c++){
                unsigned m = __ballot_sync(FULLM, (g>>c)&1u);
                if ((g>>c)&1u){
                    int pos = base + __popc(m & ((1u<<lane)-1u));
                    if (pos < CAP){
                        int e = (i*1024 + (int)tid)*4 + c;
                        int a = e >> 14, rem = e & 16383;
                        int y = rem >> 7, x = rem & 127;
                        float x1,y1,x2,y2,ws,hs;
                        decode_box(pred,b,a,y,x,imh,imw,x1,y1,x2,y2,ws,hs);
                        float scv = (c==0)?v.x:((c==1)?v.y:((c==2)?v.z:v.w));
                        unsigned key = keyOf(scv);
                        if (!(ws >= minsz && hs >= minsz)) key = keyOf(-1e30f);
                        unsigned refidx = (unsigned)((y*WW + x)*AA + a);
                        items[pos] = ((unsigned long long)key << 32) | (unsigned)(~refidx);
                    }
                }
                base += __popc(m);
            }
        }
    }
    __syncthreads();

    // ---- Phase S: bitonic sort 8192 desc (regs/shfl + smem in-place) ----
    unsigned long long r[8];
    #pragma unroll
    for (int c=0;c<8;c++) r[c] = items[tid*8u + c];
    reg_stage<1u>(r, tid, 2u);
    reg_stage<2u>(r, tid, 4u);
    reg_stage<4u>(r, tid, 8u);
    reg_stage<8u>(r, tid, 16u);
    reg_stage<16u>(r, tid, 32u);
    reg_stage<32u>(r, tid, 64u);
    reg_stage<64u>(r, tid, 128u);
    reg_stage<128u>(r, tid, 256u);
    for (unsigned k=512u; k<=(unsigned)CAP; k<<=1){
        #pragma unroll
        for (int c=0;c<8;c++) items[tid*8u+c] = r[c];
        __syncthreads();
        for (unsigned j=k>>1; j>=256u; j>>=1){
            #pragma unroll
            for (int q4=0; q4<4; q4++){
                unsigned q = (unsigned)q4*1024u + tid;
                unsigned t = ((q & ~(j-1u)) << 1) | (q & (j-1u));
                unsigned ixj = t | j;
                unsigned long long va = items[t], vb = items[ixj];
                bool d = ((t & k) == 0u);
                if ((va < vb) == d){ items[t]=vb; items[ixj]=va; }
            }
            __syncthreads();
        }
        #pragma unroll
        for (int c=0;c<8;c++) r[c] = items[tid*8u+c];
        reg_stage<128u>(r, tid, k);
    }
    // write back sorted items (keys needed by NMS validity test)
    #pragma unroll
    for (int c=0;c<8;c++) items[tid*8u+c] = r[c];

    // ---- decode top-PRE candidate boxes into smem ----
    unsigned negk = keyOf(-1e30f);
    #pragma unroll
    for (int c=0;c<8;c++){
        int i = (int)tid*8 + c;
        if (i < PRE){
            unsigned key = (unsigned)(r[c] >> 32);
            float4 box = make_float4(0.f,0.f,0.f,0.f);
            if (key > negk){
                unsigned refidx = ~((unsigned)r[c]);
                int a = (int)(refidx % AA);
                int cell = (int)(refidx / AA);
                int x = cell & 127, y = cell >> 7;
                float x1,y1,x2,y2,ws,hs;
                decode_box(pred,b,a,y,x,imh,imw,x1,y1,x2,y2,ws,hs);
                box = make_float4(x1,y1,x2,y2);
            }
            boxes[i] = box;
        }
    }
    if (tid==0) s_nk = 0;
    __syncthreads();

    // ---- Phase N: incremental sweep NMS ----
    int nk = 0;
    const int NCHUNK = (PRE + 31) / 32;
    for (int ch = 0; ch < NCHUNK; ch++){
        int ci = ch*32 + lane;
        float4 bx = make_float4(0.f,0.f,0.f,0.f);
        bool valid = false;
        if (ci < PRE){
            bx = boxes[ci];
            valid = (((unsigned)(items[ci] >> 32)) > negk);
        }
        float area = (bx.z-bx.x+1.0f)*(bx.w-bx.y+1.0f);
        // phase 1: test candidate vs kept boxes, striped over 32 warps
        bool sup = !valid;
        for (int j = wid; j < nk; j += 32){
            if (__all_sync(FULLM, sup)) break;
            float4 kb = s_kept[j];
            float ka = s_karea[j];
            float xx1=fmaxf(kb.x,bx.x), yy1=fmaxf(kb.y,bx.y);
            float xx2=fminf(kb.z,bx.z), yy2=fminf(kb.w,bx.w);
            float inter = fmaxf(xx2-xx1+1.0f,0.0f)*fmaxf(yy2-yy1+1.0f,0.0f);
            float iou = inter / fmaxf(ka + area - inter, 1e-6f);
            sup = sup | (iou > NMS_T);
        }
        unsigned m = __ballot_sync(FULLM, sup);
        if (lane == 0) s_warp[wid] = m;
        __syncthreads();
        // phase 2: warp 0 resolves the chunk serially (smem broadcast, no shfl chains)
        if (wid == 0){
            unsigned supmask = __reduce_or_sync(FULLM, s_warp[lane]);
            unsigned alivemask = ~supmask;
            while (alivemask && nk < POST){
                int bp = __ffs(alivemask) - 1;
                if (lane == bp) s_bc = bx;
                __syncwarp();
                float4 kb = s_bc;
                float ka = (kb.z-kb.x+1.0f)*(kb.w-kb.y+1.0f);
                if (lane == 0){ s_kept[nk] = kb; s_karea[nk] = ka; }
                nk++;
                alivemask &= ~(1u << bp);
                if (!alivemask || nk == POST) break;
                float xx1=fmaxf(kb.x,bx.x), yy1=fmaxf(kb.y,bx.y);
                float xx2=fminf(kb.z,bx.z), yy2=fminf(kb.w,bx.w);
                float inter = fmaxf(xx2-xx1+1.0f,0.0f)*fmaxf(yy2-yy1+1.0f,0.0f);
                float iou = inter / fmaxf(ka + area - inter, 1e-6f);
                alivemask &= ~__ballot_sync(FULLM, iou > NMS_T);
            }
            if (lane == 0) s_nk = nk;
        }
        __syncthreads();
        nk = s_nk;
        if (nk >= POST) break;
    }

    // ---- output ----
    if (tid < POST){
        int row = (b*POST + (int)tid)*5;
        float4 kb = ((int)tid < nk) ? s_kept[tid] : make_float4(0.f,0.f,0.f,0.f);
        out[row+0] = (float)b;
        out[row+1] = kb.x; out[row+2] = kb.y; out[row+3] = kb.z; out[row+4] = kb.w;
    }

    // ---- restore g_hist slab to zero for the next (graph-replayed) launch ----
    __syncthreads();
    for (int i=tid;i<NBIN;i+=1024) g_hist[b*NBIN+i] = 0u;
}

// ---------------- launcher ----------------
extern "C" void kernel_launch(void* const* d_in, const int* in_sizes, int n_in,
                              void* d_out, int out_size){
    const float* cls  = (const float*)d_in[0];
    const float* pred = (const float*)d_in[1];
    const float* info = (const float*)d_in[2];
    float* out = (float*)d_out;

    const int DYN = CAP*8 + PRE*16;   // 65536 + 96000 = 161536 bytes
    cudaFuncSetAttribute(k_back, cudaFuncAttributeMaxDynamicSharedMemorySize, DYN);

    k_hist<<<dim3(18, BB), 1024>>>(cls);
    k_back<<<BB, 1024, DYN>>>(cls, pred, info, out);
}

// round 15
// speedup vs baseline: 1.0492x; 1.0492x over previous
#include <cuda_runtime.h>
#include <math.h>
#include <stdint.h>

#define BB 32
#define AA 9
#define HH 128
#define WW 128
#define NN (AA*HH*WW)      /* 147456 */
#define PRE 6000
#define POST 300
#define CAP 8192
#define TGT 7000
#define NMS_T 0.7f
#define NBIN 2048
#define FULLM 0xFFFFFFFFu

// Anchors: generate_anchors(16,[.5,1,2],[8,16,32]) — exact integers, verified vs numpy.
__constant__ float c_anch[AA*4] = {
   -84.f, -40.f,  99.f,  55.f,
  -176.f, -88.f, 191.f, 103.f,
  -360.f,-184.f, 375.f, 199.f,
   -56.f, -56.f,  71.f,  71.f,
  -120.f,-120.f, 135.f, 135.f,
  -248.f,-248.f, 263.f, 263.f,
   -36.f, -80.f,  51.f,  95.f,
   -80.f,-168.f,  95.f, 183.f,
  -168.f,-344.f, 183.f, 359.f
};

// ---------------- device scratch ----------------
__device__ int                g_cnt[BB];
__device__ unsigned           g_thresh[BB];
__device__ unsigned           g_hist[BB*NBIN];
__device__ unsigned long long g_items[BB*CAP];
__device__ float4             g_cand[BB*PRE];
__device__ unsigned           g_candKey[BB*PRE];

__device__ __forceinline__ unsigned keyOf(float f){
    unsigned u = __float_as_uint(f);
    return (u & 0x80000000u) ? ~u : (u | 0x80000000u);
}

__device__ __forceinline__ void decode_box(const float* __restrict__ pred,
                                           int b, int a, int y, int x,
                                           float imh, float imw,
                                           float& x1, float& y1, float& x2, float& y2,
                                           float& ws, float& hs){
    float sx = (float)(x*16), sy = (float)(y*16);
    float a0 = c_anch[a*4+0]+sx, a1 = c_anch[a*4+1]+sy;
    float a2 = c_anch[a*4+2]+sx, a3 = c_anch[a*4+3]+sy;
    float aw = a2-a0+1.0f, ah = a3-a1+1.0f;
    float cx = a0+0.5f*aw,  cy = a1+0.5f*ah;
    int base = ((b*4*AA + 4*a)*HH + y)*WW + x;
    float dx = pred[base];
    float dy = pred[base +   HH*WW];
    float dw = pred[base + 2*HH*WW];
    float dh = pred[base + 3*HH*WW];
    float pcx = dx*aw+cx, pcy = dy*ah+cy;
    float pw = expf(dw)*aw, ph = expf(dh)*ah;
    x1 = pcx-0.5f*pw; y1 = pcy-0.5f*ph; x2 = pcx+0.5f*pw; y2 = pcy+0.5f*ph;
    x1 = fminf(fmaxf(x1,0.0f), imw-1.0f);
    y1 = fminf(fmaxf(y1,0.0f), imh-1.0f);
    x2 = fminf(fmaxf(x2,0.0f), imw-1.0f);
    y2 = fminf(fmaxf(y2,0.0f), imh-1.0f);
    ws = x2-x1+1.0f; hs = y2-y1+1.0f;
}

// key -> bin (monotone). Fine bins (13-bit key granularity) over key >= keyOf(0.5).
__device__ __forceinline__ unsigned binOf(unsigned key){
    if (key >= 0xBF000000u){
        unsigned b = 1024u + ((key - 0xBF000000u) >> 13);
        return b > 2047u ? 2047u : b;
    }
    unsigned b = key >> 22;
    return b > 1023u ? 1023u : b;
}
__device__ __forceinline__ unsigned binStartKey(unsigned t){
    return (t >= 1024u) ? (0xBF000000u + ((t - 1024u) << 13)) : (t << 22);
}

// ---------------- K0: zero hist + counters ----------------
__global__ void k_init(){
    int i = blockIdx.x*blockDim.x + threadIdx.x;
    if (i < BB*NBIN) g_hist[i] = 0u;
    if (i < BB) g_cnt[i] = 0;
}

// ---------------- K1: wide raw-score histogram ----------------
__global__ void k_hist(const float* __restrict__ cls){
    __shared__ unsigned h[NBIN];
    int b = blockIdx.y, tid = threadIdx.x;
    const float4* sp = (const float4*)(cls + ((size_t)b*2*AA + AA)*HH*WW);
    for (int i=tid;i<NBIN;i+=1024) h[i]=0u;
    __syncthreads();
    #pragma unroll
    for (int i=0;i<2;i++){
        float4 v = sp[(blockIdx.x*2 + i)*1024 + tid];
        atomicAdd(&h[binOf(keyOf(v.x))], 1u);
        atomicAdd(&h[binOf(keyOf(v.y))], 1u);
        atomicAdd(&h[binOf(keyOf(v.z))], 1u);
        atomicAdd(&h[binOf(keyOf(v.w))], 1u);
    }
    __syncthreads();
    for (int i=tid;i<NBIN;i+=1024)
        if (h[i]) atomicAdd(&g_hist[b*NBIN+i], h[i]);
}

// ---------------- K2: threshold per image ----------------
__global__ void k_thresh(){
    __shared__ unsigned h0[NBIN], h1[NBIN];
    int b = blockIdx.x, tid = threadIdx.x;
    for (int i=tid;i<NBIN;i+=1024) h0[i] = g_hist[b*NBIN+i];
    __syncthreads();
    unsigned *src=h0, *dst=h1;
    for (int off=1; off<NBIN; off<<=1){
        for (int i=tid;i<NBIN;i+=1024)
            dst[i] = src[i] + ((i+off<NBIN)? src[i+off] : 0u);
        __syncthreads();
        unsigned* t = src; src = dst; dst = t;
    }
    for (int i=tid;i<NBIN;i+=1024){
        unsigned si = src[i];
        unsigned nx = (i+1<NBIN)? src[i+1] : 0u;
        if (si >= TGT && nx < TGT) g_thresh[b] = binStartKey((unsigned)i);
    }
}

// ---------------- K3: compact raw>=t0, decode+filter survivors only ------------
__global__ void k_compact(const float* __restrict__ cls, const float* __restrict__ pred,
                          const float* __restrict__ info){
    __shared__ int s_wbase[32];
    __shared__ int s_gbase;
    int b = blockIdx.y, tid = threadIdx.x, lane = tid & 31, wid = tid >> 5;
    unsigned K = g_thresh[b];
    const float4* sp = (const float4*)(cls + ((size_t)b*2*AA + AA)*HH*WW);
    float imh = __ldg(&info[b*3+0]);
    float imw = __ldg(&info[b*3+1]);
    float minsz = 16.0f*__ldg(&info[b*3+2]);

    float s[16];
    unsigned okbits = 0u;
    #pragma unroll
    for (int i=0;i<4;i++){
        int f = (blockIdx.x*4 + i)*1024 + tid;
        float4 v = sp[f];
        s[i*4+0]=v.x; s[i*4+1]=v.y; s[i*4+2]=v.z; s[i*4+3]=v.w;
        if (keyOf(v.x) >= K) okbits |= 1u << (i*4+0);
        if (keyOf(v.y) >= K) okbits |= 1u << (i*4+1);
        if (keyOf(v.z) >= K) okbits |= 1u << (i*4+2);
        if (keyOf(v.w) >= K) okbits |= 1u << (i*4+3);
    }
    int wtot = __reduce_add_sync(FULLM, __popc(okbits));
    if (lane==0) s_wbase[wid] = wtot;
    __syncthreads();
    if (tid==0){
        int run = 0;
        #pragma unroll
        for (int w=0;w<32;w++){ int t = s_wbase[w]; s_wbase[w] = run; run += t; }
        s_gbase = atomicAdd(&g_cnt[b], run);
    }
    __syncthreads();
    int base = s_gbase + s_wbase[wid];
    #pragma unroll
    for (int sl=0; sl<16; sl++){
        bool ok = (okbits >> sl) & 1u;
        unsigned m = __ballot_sync(FULLM, ok);
        if (ok){
            int pos = base + __popc(m & ((1u<<lane)-1u));
            if (pos < CAP){
                int i = sl >> 2, c = sl & 3;
                int f = (blockIdx.x*4 + i)*1024 + tid;
                int e = f*4 + c;
                int a = e >> 14, rem = e & 16383;
                int y = rem >> 7, x = rem & 127;
                float x1,y1,x2,y2,ws,hs;
                decode_box(pred,b,a,y,x,imh,imw,x1,y1,x2,y2,ws,hs);
                unsigned key = keyOf(s[sl]);
                if (!(ws >= minsz && hs >= minsz)) key = keyOf(-1e30f);
                unsigned refidx = (unsigned)((y*WW + x)*AA + a);
                g_items[b*CAP + pos] =
                    ((unsigned long long)key << 32) | (unsigned)(~refidx);
            }
        }
        base += __popc(m);
    }
}

// ---------------- K4: 512-thread / 16-item bitonic sort (no spills) -----------
// Thread owns 16 contiguous items [tid*16, tid*16+16). 512 threads -> up to 128
// regs/thread, so the 32-reg data set + shfl temps stay in registers.
template<unsigned J>
__device__ __forceinline__ void reg16(unsigned long long r[16], unsigned tid, unsigned k){
    if constexpr (J >= 16u){
        constexpr unsigned lm = J >> 4;     // lane distance (1..16 for J=16..256)
        bool amLow = ((tid & lm) == 0u);
        #pragma unroll
        for (int c=0;c<16;c++){
            unsigned long long other = __shfl_xor_sync(FULLM, r[c], lm);
            bool d = (((tid*16u + (unsigned)c) & k) == 0u);  // desc
            bool takeMax = (d == amLow);
            unsigned long long mx = (r[c] > other) ? r[c] : other;
            unsigned long long mn = (r[c] > other) ? other : r[c];
            r[c] = takeMax ? mx : mn;
        }
    } else {
        #pragma unroll
        for (int c=0;c<16;c++){
            constexpr int JJ = (int)J;
            int p = c ^ JJ;
            if (p > c){
                bool d = (((tid*16u + (unsigned)c) & k) == 0u);
                if ((r[c] < r[p]) == d){
                    unsigned long long t=r[c]; r[c]=r[p]; r[p]=t;
                }
            }
        }
    }
    if constexpr (J > 1u) reg16<J/2u>(r, tid, k);
}

__global__ void __launch_bounds__(512,1)
k_sort(const float* __restrict__ pred, const float* __restrict__ info){
    extern __shared__ unsigned long long sm[];
    int b = blockIdx.x;
    unsigned tid = threadIdx.x;
    int cnt = g_cnt[b]; if (cnt > CAP) cnt = CAP;
    unsigned long long r[16];
    #pragma unroll
    for (int c=0;c<16;c++){
        int i = (int)tid*16 + c;
        r[c] = (i < cnt) ? g_items[b*CAP + i] : 0ull;
    }
    // k = 2..512 entirely in regs/shfl (warp spans 512 items), no barriers
    reg16<1u>(r, tid, 2u);
    reg16<2u>(r, tid, 4u);
    reg16<4u>(r, tid, 8u);
    reg16<8u>(r, tid, 16u);
    reg16<16u>(r, tid, 32u);
    reg16<32u>(r, tid, 64u);
    reg16<64u>(r, tid, 128u);
    reg16<128u>(r, tid, 256u);
    reg16<256u>(r, tid, 512u);
    // k = 1024..8192: smem passes for j>=512, then regs/shfl from J=256
    for (unsigned k=1024u; k<=(unsigned)CAP; k<<=1){
        #pragma unroll
        for (int c=0;c<16;c++) sm[tid*16u+c] = r[c];
        __syncthreads();
        for (unsigned j=k>>1; j>=512u; j>>=1){
            #pragma unroll
            for (int q8=0; q8<8; q8++){
                unsigned q = (unsigned)q8*512u + tid;            // 4096 pairs
                unsigned t = ((q & ~(j-1u)) << 1) | (q & (j-1u));
                unsigned ixj = t | j;
                unsigned long long va = sm[t], vb = sm[ixj];
                bool d = ((t & k) == 0u);
                if ((va < vb) == d){ sm[t]=vb; sm[ixj]=va; }
            }
            __syncthreads();
        }
        #pragma unroll
        for (int c=0;c<16;c++) r[c] = sm[tid*16u+c];
        reg16<256u>(r, tid, k);
    }
    // r = globally sorted desc, ranks tid*16+c. Decode top-PRE candidates.
    float imh = __ldg(&info[b*3+0]);
    float imw = __ldg(&info[b*3+1]);
    unsigned negk = keyOf(-1e30f);
    #pragma unroll
    for (int c=0;c<16;c++){
        int i = (int)tid*16 + c;
        if (i < PRE){
            unsigned key = (unsigned)(r[c] >> 32);
            float4 box = make_float4(0.f,0.f,0.f,0.f);
            if (key > negk){
                unsigned refidx = ~((unsigned)r[c]);
                int a = (int)(refidx % AA);
                int cell = (int)(refidx / AA);
                int x = cell & 127, y = cell >> 7;
                float x1,y1,x2,y2,ws,hs;
                decode_box(pred,b,a,y,x,imh,imw,x1,y1,x2,y2,ws,hs);
                box = make_float4(x1,y1,x2,y2);
            }
            g_cand[b*PRE+i]    = box;
            g_candKey[b*PRE+i] = key;
        }
    }
}

// ---------------- K5: incremental sweep NMS ----------------
#define NMST 512
__global__ void __launch_bounds__(NMST,1) k_nms(float* __restrict__ out){
    __shared__ float4   s_kept[POST];
    __shared__ float    s_karea[POST];
    __shared__ float4   s_bc;
    __shared__ unsigned s_warp[NMST/32];
    __shared__ int      s_nk;
    int b = blockIdx.x, tid = threadIdx.x, lane = tid & 31, wid = tid >> 5;
    unsigned negk = keyOf(-1e30f);
    if (tid == 0) s_nk = 0;
    __syncthreads();

    int nk = 0;
    const int NCHUNK = (PRE + 31) / 32;
    for (int ch = 0; ch < NCHUNK; ch++){
        int ci = ch*32 + lane;
        float4 bx = make_float4(0.f,0.f,0.f,0.f);
        bool valid = false;
        if (ci < PRE){
            bx = g_cand[b*PRE + ci];
            valid = (g_candKey[b*PRE + ci] > negk);
        }
        float area = (bx.z-bx.x+1.0f)*(bx.w-bx.y+1.0f);
        // phase 1: test candidates vs kept boxes, striped over 16 warps
        bool sup = !valid;
        for (int j = wid; j < nk; j += NMST/32){
            if (__all_sync(FULLM, sup)) break;
            float4 kb = s_kept[j];
            float ka = s_karea[j];
            float xx1=fmaxf(kb.x,bx.x), yy1=fmaxf(kb.y,bx.y);
            float xx2=fminf(kb.z,bx.z), yy2=fminf(kb.w,bx.w);
            float inter = fmaxf(xx2-xx1+1.0f,0.0f)*fmaxf(yy2-yy1+1.0f,0.0f);
            float iou = inter / fmaxf(ka + area - inter, 1e-6f);
            sup = sup | (iou > NMS_T);
        }
        unsigned m = __ballot_sync(FULLM, sup);
        if (lane == 0) s_warp[wid] = m;
        __syncthreads();
        // phase 2: warp 0 resolves the chunk serially
        if (wid == 0){
            unsigned v = (lane < NMST/32) ? s_warp[lane] : 0u;
            unsigned supmask = __reduce_or_sync(FULLM, v);
            unsigned alivemask = ~supmask;
            while (alivemask && nk < POST){
                int bp = __ffs(alivemask) - 1;
                if (lane == bp) s_bc = bx;
                __syncwarp();
                float4 kb = s_bc;
                float ka = (kb.z-kb.x+1.0f)*(kb.w-kb.y+1.0f);
                if (lane == 0){ s_kept[nk] = kb; s_karea[nk] = ka; }
                nk++;
                alivemask &= ~(1u << bp);
                if (!alivemask || nk == POST) break;
                float xx1=fmaxf(kb.x,bx.x), yy1=fmaxf(kb.y,bx.y);
                float xx2=fminf(kb.z,bx.z), yy2=fminf(kb.w,bx.w);
                float inter = fmaxf(xx2-xx1+1.0f,0.0f)*fmaxf(yy2-yy1+1.0f,0.0f);
                float iou = inter / fmaxf(ka + area - inter, 1e-6f);
                alivemask &= ~__ballot_sync(FULLM, iou > NMS_T);
            }
            if (lane == 0) s_nk = nk;
        }
        __syncthreads();
        nk = s_nk;
        if (nk >= POST) break;
    }

    if (tid < POST){
        int row = (b*POST + tid)*5;
        float4 kb = (tid < nk) ? s_kept[tid] : make_float4(0.f,0.f,0.f,0.f);
        out[row+0] = (float)b;
        out[row+1] = kb.x; out[row+2] = kb.y; out[row+3] = kb.z; out[row+4] = kb.w;
    }
}

// ---------------- launcher ----------------
extern "C" void kernel_launch(void* const* d_in, const int* in_sizes, int n_in,
                              void* d_out, int out_size){
    const float* cls  = (const float*)d_in[0];
    const float* pred = (const float*)d_in[1];
    const float* info = (const float*)d_in[2];
    float* out = (float*)d_out;

    cudaFuncSetAttribute(k_sort, cudaFuncAttributeMaxDynamicSharedMemorySize, CAP*8);

    k_init<<<BB*NBIN/1024, 1024>>>();
    k_hist<<<dim3(18, BB), 1024>>>(cls);
    k_thresh<<<BB, 1024>>>();
    k_compact<<<dim3(9, BB), 1024>>>(cls, pred, info);
    k_sort<<<BB, 512, CAP*8>>>(pred, info);
    k_nms<<<BB, NMST>>>(out);
}

// round 16
// speedup vs baseline: 1.1343x; 1.0811x over previous
#include <cuda_runtime.h>
#include <math.h>
#include <stdint.h>

#define BB 32
#define AA 9
#define HH 128
#define WW 128
#define NN (AA*HH*WW)      /* 147456 */
#define PRE 6000
#define POST 300
#define CAP 8192
#define TGT 7000
#define NMS_T 0.7f
#define NBIN 2048
#define FULLM 0xFFFFFFFFu

// Anchors: generate_anchors(16,[.5,1,2],[8,16,32]) — exact integers, verified vs numpy.
__constant__ float c_anch[AA*4] = {
   -84.f, -40.f,  99.f,  55.f,
  -176.f, -88.f, 191.f, 103.f,
  -360.f,-184.f, 375.f, 199.f,
   -56.f, -56.f,  71.f,  71.f,
  -120.f,-120.f, 135.f, 135.f,
  -248.f,-248.f, 263.f, 263.f,
   -36.f, -80.f,  51.f,  95.f,
   -80.f,-168.f,  95.f, 183.f,
  -168.f,-344.f, 183.f, 359.f
};

// ---------------- device scratch ----------------
__device__ int                g_cnt[BB];
__device__ unsigned           g_thresh[BB];
__device__ unsigned           g_hist[BB*NBIN];
__device__ unsigned long long g_items[BB*CAP];
__device__ float4             g_cand[BB*PRE];
__device__ unsigned           g_candKey[BB*PRE];

__device__ __forceinline__ unsigned keyOf(float f){
    unsigned u = __float_as_uint(f);
    return (u & 0x80000000u) ? ~u : (u | 0x80000000u);
}

__device__ __forceinline__ void decode_box(const float* __restrict__ pred,
                                           int b, int a, int y, int x,
                                           float imh, float imw,
                                           float& x1, float& y1, float& x2, float& y2,
                                           float& ws, float& hs){
    float sx = (float)(x*16), sy = (float)(y*16);
    float a0 = c_anch[a*4+0]+sx, a1 = c_anch[a*4+1]+sy;
    float a2 = c_anch[a*4+2]+sx, a3 = c_anch[a*4+3]+sy;
    float aw = a2-a0+1.0f, ah = a3-a1+1.0f;
    float cx = a0+0.5f*aw,  cy = a1+0.5f*ah;
    int base = ((b*4*AA + 4*a)*HH + y)*WW + x;
    float dx = pred[base];
    float dy = pred[base +   HH*WW];
    float dw = pred[base + 2*HH*WW];
    float dh = pred[base + 3*HH*WW];
    float pcx = dx*aw+cx, pcy = dy*ah+cy;
    float pw = expf(dw)*aw, ph = expf(dh)*ah;
    x1 = pcx-0.5f*pw; y1 = pcy-0.5f*ph; x2 = pcx+0.5f*pw; y2 = pcy+0.5f*ph;
    x1 = fminf(fmaxf(x1,0.0f), imw-1.0f);
    y1 = fminf(fmaxf(y1,0.0f), imh-1.0f);
    x2 = fminf(fmaxf(x2,0.0f), imw-1.0f);
    y2 = fminf(fmaxf(y2,0.0f), imh-1.0f);
    ws = x2-x1+1.0f; hs = y2-y1+1.0f;
}

// key -> bin (monotone). Fine bins (13-bit key granularity) over key >= keyOf(0.5).
__device__ __forceinline__ unsigned binOf(unsigned key){
    if (key >= 0xBF000000u){
        unsigned b = 1024u + ((key - 0xBF000000u) >> 13);
        return b > 2047u ? 2047u : b;
    }
    unsigned b = key >> 22;
    return b > 1023u ? 1023u : b;
}
__device__ __forceinline__ unsigned binStartKey(unsigned t){
    return (t >= 1024u) ? (0xBF000000u + ((t - 1024u) << 13)) : (t << 22);
}

// ---------------- K0: zero hist + counters ----------------
__global__ void k_init(){
    int i = blockIdx.x*blockDim.x + threadIdx.x;
    if (i < BB*NBIN) g_hist[i] = 0u;
    if (i < BB) g_cnt[i] = 0;
}

// ---------------- K1: wide raw-score histogram ----------------
__global__ void k_hist(const float* __restrict__ cls){
    __shared__ unsigned h[NBIN];
    int b = blockIdx.y, tid = threadIdx.x;
    const float4* sp = (const float4*)(cls + ((size_t)b*2*AA + AA)*HH*WW);
    for (int i=tid;i<NBIN;i+=1024) h[i]=0u;
    __syncthreads();
    #pragma unroll
    for (int i=0;i<2;i++){
        float4 v = sp[(blockIdx.x*2 + i)*1024 + tid];
        atomicAdd(&h[binOf(keyOf(v.x))], 1u);
        atomicAdd(&h[binOf(keyOf(v.y))], 1u);
        atomicAdd(&h[binOf(keyOf(v.z))], 1u);
        atomicAdd(&h[binOf(keyOf(v.w))], 1u);
    }
    __syncthreads();
    for (int i=tid;i<NBIN;i+=1024)
        if (h[i]) atomicAdd(&g_hist[b*NBIN+i], h[i]);
}

// ---------------- K2: threshold per image ----------------
__global__ void k_thresh(){
    __shared__ unsigned h0[NBIN], h1[NBIN];
    int b = blockIdx.x, tid = threadIdx.x;
    for (int i=tid;i<NBIN;i+=1024) h0[i] = g_hist[b*NBIN+i];
    __syncthreads();
    unsigned *src=h0, *dst=h1;
    for (int off=1; off<NBIN; off<<=1){
        for (int i=tid;i<NBIN;i+=1024)
            dst[i] = src[i] + ((i+off<NBIN)? src[i+off] : 0u);
        __syncthreads();
        unsigned* t = src; src = dst; dst = t;
    }
    for (int i=tid;i<NBIN;i+=1024){
        unsigned si = src[i];
        unsigned nx = (i+1<NBIN)? src[i+1] : 0u;
        if (si >= TGT && nx < TGT) g_thresh[b] = binStartKey((unsigned)i);
    }
}

// ---------------- K3: compact raw>=t0, decode+filter survivors only ------------
__global__ void k_compact(const float* __restrict__ cls, const float* __restrict__ pred,
                          const float* __restrict__ info){
    __shared__ int s_wbase[32];
    __shared__ int s_gbase;
    int b = blockIdx.y, tid = threadIdx.x, lane = tid & 31, wid = tid >> 5;
    unsigned K = g_thresh[b];
    const float4* sp = (const float4*)(cls + ((size_t)b*2*AA + AA)*HH*WW);
    float imh = __ldg(&info[b*3+0]);
    float imw = __ldg(&info[b*3+1]);
    float minsz = 16.0f*__ldg(&info[b*3+2]);

    float s[16];
    unsigned okbits = 0u;
    #pragma unroll
    for (int i=0;i<4;i++){
        int f = (blockIdx.x*4 + i)*1024 + tid;
        float4 v = sp[f];
        s[i*4+0]=v.x; s[i*4+1]=v.y; s[i*4+2]=v.z; s[i*4+3]=v.w;
        if (keyOf(v.x) >= K) okbits |= 1u << (i*4+0);
        if (keyOf(v.y) >= K) okbits |= 1u << (i*4+1);
        if (keyOf(v.z) >= K) okbits |= 1u << (i*4+2);
        if (keyOf(v.w) >= K) okbits |= 1u << (i*4+3);
    }
    int wtot = __reduce_add_sync(FULLM, __popc(okbits));
    if (lane==0) s_wbase[wid] = wtot;
    __syncthreads();
    if (tid==0){
        int run = 0;
        #pragma unroll
        for (int w=0;w<32;w++){ int t = s_wbase[w]; s_wbase[w] = run; run += t; }
        s_gbase = atomicAdd(&g_cnt[b], run);
    }
    __syncthreads();
    int base = s_gbase + s_wbase[wid];
    #pragma unroll
    for (int sl=0; sl<16; sl++){
        bool ok = (okbits >> sl) & 1u;
        unsigned m = __ballot_sync(FULLM, ok);
        if (ok){
            int pos = base + __popc(m & ((1u<<lane)-1u));
            if (pos < CAP){
                int i = sl >> 2, c = sl & 3;
                int f = (blockIdx.x*4 + i)*1024 + tid;
                int e = f*4 + c;
                int a = e >> 14, rem = e & 16383;
                int y = rem >> 7, x = rem & 127;
                float x1,y1,x2,y2,ws,hs;
                decode_box(pred,b,a,y,x,imh,imw,x1,y1,x2,y2,ws,hs);
                unsigned key = keyOf(s[sl]);
                if (!(ws >= minsz && hs >= minsz)) key = keyOf(-1e30f);
                unsigned refidx = (unsigned)((y*WW + x)*AA + a);
                g_items[b*CAP + pos] =
                    ((unsigned long long)key << 32) | (unsigned)(~refidx);
            }
        }
        base += __popc(m);
    }
}

// ---------------- K4: register/shfl bitonic sort (R8 proven: 1024thr, 8 items) --
template<unsigned J>
__device__ __forceinline__ void reg_stage(unsigned long long r[8], unsigned tid, unsigned k){
    if constexpr (J >= 8u){
        constexpr unsigned lm = J >> 3;
        bool amLow = ((tid & lm) == 0u);
        #pragma unroll
        for (int c=0;c<8;c++){
            unsigned long long other = __shfl_xor_sync(FULLM, r[c], lm);
            bool d = (((tid*8u + (unsigned)c) & k) == 0u);  // desc
            bool takeMax = (d == amLow);
            unsigned long long mx = (r[c] > other) ? r[c] : other;
            unsigned long long mn = (r[c] > other) ? other : r[c];
            r[c] = takeMax ? mx : mn;
        }
    } else {
        #pragma unroll
        for (int c=0;c<8;c++){
            constexpr int JJ = (int)J;
            int p = c ^ JJ;
            if (p > c){
                bool d = (((tid*8u + (unsigned)c) & k) == 0u);
                if ((r[c] < r[p]) == d){
                    unsigned long long t=r[c]; r[c]=r[p]; r[p]=t;
                }
            }
        }
    }
    if constexpr (J > 1u) reg_stage<J/2u>(r, tid, k);
}

__global__ void __launch_bounds__(1024,1)
k_sort(const float* __restrict__ pred, const float* __restrict__ info){
    extern __shared__ unsigned long long sm[];
    int b = blockIdx.x;
    unsigned tid = threadIdx.x;
    int cnt = g_cnt[b]; if (cnt > CAP) cnt = CAP;
    unsigned long long r[8];
    #pragma unroll
    for (int c=0;c<8;c++){
        int i = (int)tid*8 + c;
        r[c] = (i < cnt) ? g_items[b*CAP + i] : 0ull;
    }
    reg_stage<1u>(r, tid, 2u);
    reg_stage<2u>(r, tid, 4u);
    reg_stage<4u>(r, tid, 8u);
    reg_stage<8u>(r, tid, 16u);
    reg_stage<16u>(r, tid, 32u);
    reg_stage<32u>(r, tid, 64u);
    reg_stage<64u>(r, tid, 128u);
    reg_stage<128u>(r, tid, 256u);
    for (unsigned k=512u; k<=(unsigned)CAP; k<<=1){
        #pragma unroll
        for (int c=0;c<8;c++) sm[tid*8u+c] = r[c];
        __syncthreads();
        for (unsigned j=k>>1; j>=256u; j>>=1){
            #pragma unroll
            for (int q4=0; q4<4; q4++){
                unsigned q = (unsigned)q4*1024u + tid;
                unsigned t = ((q & ~(j-1u)) << 1) | (q & (j-1u));
                unsigned ixj = t | j;
                unsigned long long va = sm[t], vb = sm[ixj];
                bool d = ((t & k) == 0u);
                if ((va < vb) == d){ sm[t]=vb; sm[ixj]=va; }
            }
            __syncthreads();
        }
        #pragma unroll
        for (int c=0;c<8;c++) r[c] = sm[tid*8u+c];
        reg_stage<128u>(r, tid, k);
    }
    float imh = __ldg(&info[b*3+0]);
    float imw = __ldg(&info[b*3+1]);
    unsigned negk = keyOf(-1e30f);
    #pragma unroll
    for (int c=0;c<8;c++){
        int i = (int)tid*8 + c;
        if (i < PRE){
            unsigned key = (unsigned)(r[c] >> 32);
            float4 box = make_float4(0.f,0.f,0.f,0.f);
            if (key > negk){
                unsigned refidx = ~((unsigned)r[c]);
                int a = (int)(refidx % AA);
                int cell = (int)(refidx / AA);
                int x = cell & 127, y = cell >> 7;
                float x1,y1,x2,y2,ws,hs;
                decode_box(pred,b,a,y,x,imh,imw,x1,y1,x2,y2,ws,hs);
                box = make_float4(x1,y1,x2,y2);
            }
            g_cand[b*PRE+i]    = box;
            g_candKey[b*PRE+i] = key;
        }
    }
}

// ---------------- K5: incremental sweep NMS (1024 thr, smem candidates) --------
#define NMST 1024
#define NWRP (NMST/32)
#define NCHUNK ((PRE + 31) / 32)     /* 188 */
__global__ void __launch_bounds__(NMST,1) k_nms(float* __restrict__ out){
    extern __shared__ char smc[];
    float4*   cbox   = (float4*)smc;                    // PRE*16 = 96000 B
    unsigned* cvalid = (unsigned*)(smc + PRE*16);       // NCHUNK words
    __shared__ float4   s_kept[POST];
    __shared__ float    s_karea[POST];
    __shared__ float4   s_bc;
    __shared__ unsigned s_warp[NWRP];
    __shared__ int      s_nk;
    int b = blockIdx.x, tid = threadIdx.x, lane = tid & 31, wid = tid >> 5;
    unsigned negk = keyOf(-1e30f);

    // preload candidates + validity bitmask (coalesced, once)
    for (int i=tid; i<PRE; i+=NMST) cbox[i] = g_cand[b*PRE+i];
    for (int i=tid; i<NCHUNK*32; i+=NMST){
        bool v = (i < PRE) && (g_candKey[b*PRE+i] > negk);
        unsigned m = __ballot_sync(FULLM, v);
        if (lane == 0) cvalid[i>>5] = m;
    }
    if (tid == 0) s_nk = 0;
    __syncthreads();

    int nk = 0;
    for (int ch = 0; ch < NCHUNK; ch++){
        int ci = ch*32 + lane;
        float4 bx = (ci < PRE) ? cbox[ci] : make_float4(0.f,0.f,0.f,0.f);
        bool valid = (cvalid[ch] >> lane) & 1u;
        float area = (bx.z-bx.x+1.0f)*(bx.w-bx.y+1.0f);
        // phase 1: candidates vs kept boxes, striped over 32 warps
        bool sup = !valid;
        for (int j = wid; j < nk; j += NWRP){
            float4 kb = s_kept[j];
            float ka = s_karea[j];
            float xx1=fmaxf(kb.x,bx.x), yy1=fmaxf(kb.y,bx.y);
            float xx2=fminf(kb.z,bx.z), yy2=fminf(kb.w,bx.w);
            float inter = fmaxf(xx2-xx1+1.0f,0.0f)*fmaxf(yy2-yy1+1.0f,0.0f);
            float iou = inter / fmaxf(ka + area - inter, 1e-6f);
            sup = sup | (iou > NMS_T);
        }
        unsigned m = __ballot_sync(FULLM, sup);
        if (lane == 0) s_warp[wid] = m;
        __syncthreads();
        // phase 2: warp 0 resolves the chunk serially
        if (wid == 0){
            unsigned v = s_warp[lane];       // NWRP==32
            unsigned supmask = __reduce_or_sync(FULLM, v);
            unsigned alivemask = ~supmask;
            while (alivemask && nk < POST){
                int bp = __ffs(alivemask) - 1;
                if (lane == bp) s_bc = bx;
                __syncwarp();
                float4 kb = s_bc;
                float ka = (kb.z-kb.x+1.0f)*(kb.w-kb.y+1.0f);
                if (lane == 0){ s_kept[nk] = kb; s_karea[nk] = ka; }
                nk++;
                alivemask &= ~(1u << bp);
                if (!alivemask || nk == POST) break;
                float xx1=fmaxf(kb.x,bx.x), yy1=fmaxf(kb.y,bx.y);
                float xx2=fminf(kb.z,bx.z), yy2=fminf(kb.w,bx.w);
                float inter = fmaxf(xx2-xx1+1.0f,0.0f)*fmaxf(yy2-yy1+1.0f,0.0f);
                float iou = inter / fmaxf(ka + area - inter, 1e-6f);
                alivemask &= ~__ballot_sync(FULLM, iou > NMS_T);
            }
            if (lane == 0) s_nk = nk;
        }
        __syncthreads();
        nk = s_nk;
        if (nk >= POST) break;
    }

    if (tid < POST){
        int row = (b*POST + tid)*5;
        float4 kb = (tid < nk) ? s_kept[tid] : make_float4(0.f,0.f,0.f,0.f);
        out[row+0] = (float)b;
        out[row+1] = kb.x; out[row+2] = kb.y; out[row+3] = kb.z; out[row+4] = kb.w;
    }
}

// ---------------- launcher ----------------
extern "C" void kernel_launch(void* const* d_in, const int* in_sizes, int n_in,
                              void* d_out, int out_size){
    const float* cls  = (const float*)d_in[0];
    const float* pred = (const float*)d_in[1];
    const float* info = (const float*)d_in[2];
    float* out = (float*)d_out;

    const int NMS_DYN = PRE*16 + NCHUNK*4;   // 96000 + 752
    cudaFuncSetAttribute(k_sort, cudaFuncAttributeMaxDynamicSharedMemorySize, CAP*8);
    cudaFuncSetAttribute(k_nms,  cudaFuncAttributeMaxDynamicSharedMemorySize, NMS_DYN);

    k_init<<<BB*NBIN/1024, 1024>>>();
    k_hist<<<dim3(18, BB), 1024>>>(cls);
    k_thresh<<<BB, 1024>>>();
    k_compact<<<dim3(9, BB), 1024>>>(cls, pred, info);
    k_sort<<<BB, 1024, CAP*8>>>(pred, info);
    k_nms<<<BB, NMST, NMS_DYN>>>(out);
}

// round 17
// speedup vs baseline: 1.1865x; 1.0460x over previous
#include <cuda_runtime.h>
#include <math.h>
#include <stdint.h>

#define BB 32
#define AA 9
#define HH 128
#define WW 128
#define NN (AA*HH*WW)      /* 147456 */
#define PRE 6000
#define POST 300
#define CAP 8192
#define TGT 7000
#define NMS_T 0.7f
#define NBIN 2048
#define FULLM 0xFFFFFFFFu
#define NCHUNK ((PRE + 31) / 32)     /* 188 */

// Anchors: generate_anchors(16,[.5,1,2],[8,16,32]) — exact integers, verified vs numpy.
__constant__ float c_anch[AA*4] = {
   -84.f, -40.f,  99.f,  55.f,
  -176.f, -88.f, 191.f, 103.f,
  -360.f,-184.f, 375.f, 199.f,
   -56.f, -56.f,  71.f,  71.f,
  -120.f,-120.f, 135.f, 135.f,
  -248.f,-248.f, 263.f, 263.f,
   -36.f, -80.f,  51.f,  95.f,
   -80.f,-168.f,  95.f, 183.f,
  -168.f,-344.f, 183.f, 359.f
};

// ---------------- device scratch ----------------
// Zero-initialized at module load; k_sortnms re-zeroes g_hist[b] and g_cnt[b]
// at the end of every pipeline, so the "starts zeroed" invariant holds across
// graph replays deterministically.
__device__ int                g_cnt[BB];
__device__ unsigned           g_thresh[BB];
__device__ unsigned           g_hist[BB*NBIN];
__device__ unsigned long long g_items[BB*CAP];

__device__ __forceinline__ unsigned keyOf(float f){
    unsigned u = __float_as_uint(f);
    return (u & 0x80000000u) ? ~u : (u | 0x80000000u);
}

__device__ __forceinline__ void decode_box(const float* __restrict__ pred,
                                           int b, int a, int y, int x,
                                           float imh, float imw,
                                           float& x1, float& y1, float& x2, float& y2,
                                           float& ws, float& hs){
    float sx = (float)(x*16), sy = (float)(y*16);
    float a0 = c_anch[a*4+0]+sx, a1 = c_anch[a*4+1]+sy;
    float a2 = c_anch[a*4+2]+sx, a3 = c_anch[a*4+3]+sy;
    float aw = a2-a0+1.0f, ah = a3-a1+1.0f;
    float cx = a0+0.5f*aw,  cy = a1+0.5f*ah;
    int base = ((b*4*AA + 4*a)*HH + y)*WW + x;
    float dx = pred[base];
    float dy = pred[base +   HH*WW];
    float dw = pred[base + 2*HH*WW];
    float dh = pred[base + 3*HH*WW];
    float pcx = dx*aw+cx, pcy = dy*ah+cy;
    float pw = expf(dw)*aw, ph = expf(dh)*ah;
    x1 = pcx-0.5f*pw; y1 = pcy-0.5f*ph; x2 = pcx+0.5f*pw; y2 = pcy+0.5f*ph;
    x1 = fminf(fmaxf(x1,0.0f), imw-1.0f);
    y1 = fminf(fmaxf(y1,0.0f), imh-1.0f);
    x2 = fminf(fmaxf(x2,0.0f), imw-1.0f);
    y2 = fminf(fmaxf(y2,0.0f), imh-1.0f);
    ws = x2-x1+1.0f; hs = y2-y1+1.0f;
}

// key -> bin (monotone). Fine bins (13-bit key granularity) over key >= keyOf(0.5).
__device__ __forceinline__ unsigned binOf(unsigned key){
    if (key >= 0xBF000000u){
        unsigned b = 1024u + ((key - 0xBF000000u) >> 13);
        return b > 2047u ? 2047u : b;
    }
    unsigned b = key >> 22;
    return b > 1023u ? 1023u : b;
}
__device__ __forceinline__ unsigned binStartKey(unsigned t){
    return (t >= 1024u) ? (0xBF000000u + ((t - 1024u) << 13)) : (t << 22);
}

// ---------------- K1: wide raw-score histogram ----------------
__global__ void k_hist(const float* __restrict__ cls){
    __shared__ unsigned h[NBIN];
    int b = blockIdx.y, tid = threadIdx.x;
    const float4* sp = (const float4*)(cls + ((size_t)b*2*AA + AA)*HH*WW);
    for (int i=tid;i<NBIN;i+=1024) h[i]=0u;
    __syncthreads();
    #pragma unroll
    for (int i=0;i<2;i++){
        float4 v = sp[(blockIdx.x*2 + i)*1024 + tid];
        atomicAdd(&h[binOf(keyOf(v.x))], 1u);
        atomicAdd(&h[binOf(keyOf(v.y))], 1u);
        atomicAdd(&h[binOf(keyOf(v.z))], 1u);
        atomicAdd(&h[binOf(keyOf(v.w))], 1u);
    }
    __syncthreads();
    for (int i=tid;i<NBIN;i+=1024)
        if (h[i]) atomicAdd(&g_hist[b*NBIN+i], h[i]);
}

// ---------------- K2: threshold per image ----------------
__global__ void k_thresh(){
    __shared__ unsigned h0[NBIN], h1[NBIN];
    int b = blockIdx.x, tid = threadIdx.x;
    for (int i=tid;i<NBIN;i+=1024) h0[i] = g_hist[b*NBIN+i];
    __syncthreads();
    unsigned *src=h0, *dst=h1;
    for (int off=1; off<NBIN; off<<=1){
        for (int i=tid;i<NBIN;i+=1024)
            dst[i] = src[i] + ((i+off<NBIN)? src[i+off] : 0u);
        __syncthreads();
        unsigned* t = src; src = dst; dst = t;
    }
    for (int i=tid;i<NBIN;i+=1024){
        unsigned si = src[i];
        unsigned nx = (i+1<NBIN)? src[i+1] : 0u;
        if (si >= TGT && nx < TGT) g_thresh[b] = binStartKey((unsigned)i);
    }
}

// ---------------- K3: compact raw>=t0, decode+filter survivors only ------------
__global__ void k_compact(const float* __restrict__ cls, const float* __restrict__ pred,
                          const float* __restrict__ info){
    __shared__ int s_wbase[32];
    __shared__ int s_gbase;
    int b = blockIdx.y, tid = threadIdx.x, lane = tid & 31, wid = tid >> 5;
    unsigned K = g_thresh[b];
    const float4* sp = (const float4*)(cls + ((size_t)b*2*AA + AA)*HH*WW);
    float imh = __ldg(&info[b*3+0]);
    float imw = __ldg(&info[b*3+1]);
    float minsz = 16.0f*__ldg(&info[b*3+2]);

    float s[16];
    unsigned okbits = 0u;
    #pragma unroll
    for (int i=0;i<4;i++){
        int f = (blockIdx.x*4 + i)*1024 + tid;
        float4 v = sp[f];
        s[i*4+0]=v.x; s[i*4+1]=v.y; s[i*4+2]=v.z; s[i*4+3]=v.w;
        if (keyOf(v.x) >= K) okbits |= 1u << (i*4+0);
        if (keyOf(v.y) >= K) okbits |= 1u << (i*4+1);
        if (keyOf(v.z) >= K) okbits |= 1u << (i*4+2);
        if (keyOf(v.w) >= K) okbits |= 1u << (i*4+3);
    }
    int wtot = __reduce_add_sync(FULLM, __popc(okbits));
    if (lane==0) s_wbase[wid] = wtot;
    __syncthreads();
    if (tid==0){
        int run = 0;
        #pragma unroll
        for (int w=0;w<32;w++){ int t = s_wbase[w]; s_wbase[w] = run; run += t; }
        s_gbase = atomicAdd(&g_cnt[b], run);
    }
    __syncthreads();
    int base = s_gbase + s_wbase[wid];
    #pragma unroll
    for (int sl=0; sl<16; sl++){
        bool ok = (okbits >> sl) & 1u;
        unsigned m = __ballot_sync(FULLM, ok);
        if (ok){
            int pos = base + __popc(m & ((1u<<lane)-1u));
            if (pos < CAP){
                int i = sl >> 2, c = sl & 3;
                int f = (blockIdx.x*4 + i)*1024 + tid;
                int e = f*4 + c;
                int a = e >> 14, rem = e & 16383;
                int y = rem >> 7, x = rem & 127;
                float x1,y1,x2,y2,ws,hs;
                decode_box(pred,b,a,y,x,imh,imw,x1,y1,x2,y2,ws,hs);
                unsigned key = keyOf(s[sl]);
                if (!(ws >= minsz && hs >= minsz)) key = keyOf(-1e30f);
                unsigned refidx = (unsigned)((y*WW + x)*AA + a);
                g_items[b*CAP + pos] =
                    ((unsigned long long)key << 32) | (unsigned)(~refidx);
            }
        }
        base += __popc(m);
    }
}

// ---------------- K4: fused bitonic sort + incremental sweep NMS ---------------
template<unsigned J>
__device__ __forceinline__ void reg_stage(unsigned long long r[8], unsigned tid, unsigned k){
    if constexpr (J >= 8u){
        constexpr unsigned lm = J >> 3;
        bool amLow = ((tid & lm) == 0u);
        #pragma unroll
        for (int c=0;c<8;c++){
            unsigned long long other = __shfl_xor_sync(FULLM, r[c], lm);
            bool d = (((tid*8u + (unsigned)c) & k) == 0u);  // desc
            bool takeMax = (d == amLow);
            unsigned long long mx = (r[c] > other) ? r[c] : other;
            unsigned long long mn = (r[c] > other) ? other : r[c];
            r[c] = takeMax ? mx : mn;
        }
    } else {
        #pragma unroll
        for (int c=0;c<8;c++){
            constexpr int JJ = (int)J;
            int p = c ^ JJ;
            if (p > c){
                bool d = (((tid*8u + (unsigned)c) & k) == 0u);
                if ((r[c] < r[p]) == d){
                    unsigned long long t=r[c]; r[c]=r[p]; r[p]=t;
                }
            }
        }
    }
    if constexpr (J > 1u) reg_stage<J/2u>(r, tid, k);
}

__global__ void __launch_bounds__(1024,1)
k_sortnms(const float* __restrict__ pred, const float* __restrict__ info,
          float* __restrict__ out){
    extern __shared__ char smraw[];
    unsigned long long* sm  = (unsigned long long*)smraw;       // 64KB (sort scratch)
    float4*             cbox = (float4*)(smraw + CAP*8);        // 96KB candidates
    __shared__ unsigned cvalid[256];
    __shared__ float4   s_kept[POST];
    __shared__ float    s_karea[POST];
    __shared__ float4   s_bc;
    __shared__ unsigned s_warp[32];
    __shared__ int      s_nk;

    int b = blockIdx.x;
    unsigned tid = threadIdx.x;
    int lane = tid & 31, wid = tid >> 5;
    if (tid < 256) cvalid[tid] = 0u;
    if (tid == 0) s_nk = 0;

    // ---- sort phase ----
    int cnt = g_cnt[b]; if (cnt > CAP) cnt = CAP;
    unsigned long long r[8];
    #pragma unroll
    for (int c=0;c<8;c++){
        int i = (int)tid*8 + c;
        r[c] = (i < cnt) ? g_items[b*CAP + i] : 0ull;
    }
    reg_stage<1u>(r, tid, 2u);
    reg_stage<2u>(r, tid, 4u);
    reg_stage<4u>(r, tid, 8u);
    reg_stage<8u>(r, tid, 16u);
    reg_stage<16u>(r, tid, 32u);
    reg_stage<32u>(r, tid, 64u);
    reg_stage<64u>(r, tid, 128u);
    reg_stage<128u>(r, tid, 256u);
    for (unsigned k=512u; k<=(unsigned)CAP; k<<=1){
        #pragma unroll
        for (int c=0;c<8;c++) sm[tid*8u+c] = r[c];
        __syncthreads();
        for (unsigned j=k>>1; j>=256u; j>>=1){
            #pragma unroll
            for (int q4=0; q4<4; q4++){
                unsigned q = (unsigned)q4*1024u + tid;
                unsigned t = ((q & ~(j-1u)) << 1) | (q & (j-1u));
                unsigned ixj = t | j;
                unsigned long long va = sm[t], vb = sm[ixj];
                bool d = ((t & k) == 0u);
                if ((va < vb) == d){ sm[t]=vb; sm[ixj]=va; }
            }
            __syncthreads();
        }
        #pragma unroll
        for (int c=0;c<8;c++) r[c] = sm[tid*8u+c];
        reg_stage<128u>(r, tid, k);
    }

    // ---- decode sorted top-PRE straight from registers into smem ----
    float imh = __ldg(&info[b*3+0]);
    float imw = __ldg(&info[b*3+1]);
    unsigned negk = keyOf(-1e30f);
    unsigned vb8 = 0u;
    #pragma unroll
    for (int c=0;c<8;c++){
        int i = (int)tid*8 + c;
        if (i < PRE){
            unsigned key = (unsigned)(r[c] >> 32);
            float4 box = make_float4(0.f,0.f,0.f,0.f);
            if (key > negk){
                vb8 |= 1u << c;
                unsigned refidx = ~((unsigned)r[c]);
                int a = (int)(refidx % AA);
                int cell = (int)(refidx / AA);
                int x = cell & 127, y = cell >> 7;
                float x1,y1,x2,y2,ws,hs;
                decode_box(pred,b,a,y,x,imh,imw,x1,y1,x2,y2,ws,hs);
                box = make_float4(x1,y1,x2,y2);
            }
            cbox[i] = box;
        }
    }
    if (vb8) atomicOr(&cvalid[tid >> 2], vb8 << ((tid & 3u)*8u));
    __syncthreads();

    // ---- NMS phase: incremental sweep ----
    int nk = 0;
    for (int ch = 0; ch < NCHUNK; ch++){
        int ci = ch*32 + lane;
        float4 bx = (ci < PRE) ? cbox[ci] : make_float4(0.f,0.f,0.f,0.f);
        bool valid = (cvalid[ch] >> lane) & 1u;
        float area = (bx.z-bx.x+1.0f)*(bx.w-bx.y+1.0f);
        bool sup = !valid;
        for (int j = wid; j < nk; j += 32){
            float4 kb = s_kept[j];
            float ka = s_karea[j];
            float xx1=fmaxf(kb.x,bx.x), yy1=fmaxf(kb.y,bx.y);
            float xx2=fminf(kb.z,bx.z), yy2=fminf(kb.w,bx.w);
            float inter = fmaxf(xx2-xx1+1.0f,0.0f)*fmaxf(yy2-yy1+1.0f,0.0f);
            float iou = inter / fmaxf(ka + area - inter, 1e-6f);
            sup = sup | (iou > NMS_T);
        }
        unsigned m = __ballot_sync(FULLM, sup);
        if (lane == 0) s_warp[wid] = m;
        __syncthreads();
        if (wid == 0){
            unsigned supmask = __reduce_or_sync(FULLM, s_warp[lane]);
            unsigned alivemask = ~supmask;
            while (alivemask && nk < POST){
                int bp = __ffs(alivemask) - 1;
                if (lane == bp) s_bc = bx;
                __syncwarp();
                float4 kb = s_bc;
                float ka = (kb.z-kb.x+1.0f)*(kb.w-kb.y+1.0f);
                if (lane == 0){ s_kept[nk] = kb; s_karea[nk] = ka; }
                nk++;
                alivemask &= ~(1u << bp);
                if (!alivemask || nk == POST) break;
                float xx1=fmaxf(kb.x,bx.x), yy1=fmaxf(kb.y,bx.y);
                float xx2=fminf(kb.z,bx.z), yy2=fminf(kb.w,bx.w);
                float inter = fmaxf(xx2-xx1+1.0f,0.0f)*fmaxf(yy2-yy1+1.0f,0.0f);
                float iou = inter / fmaxf(ka + area - inter, 1e-6f);
                alivemask &= ~__ballot_sync(FULLM, iou > NMS_T);
            }
            if (lane == 0) s_nk = nk;
        }
        __syncthreads();
        nk = s_nk;
        if (nk >= POST) break;
    }

    // ---- output ----
    if (tid < POST){
        int row = (b*POST + (int)tid)*5;
        float4 kb = ((int)tid < nk) ? s_kept[tid] : make_float4(0.f,0.f,0.f,0.f);
        out[row+0] = (float)b;
        out[row+1] = kb.x; out[row+2] = kb.y; out[row+3] = kb.z; out[row+4] = kb.w;
    }

    // ---- cleanup: restore zero-state for next graph replay ----
    for (int i=tid; i<NBIN; i+=1024) g_hist[b*NBIN+i] = 0u;
    if (tid == 0) g_cnt[b] = 0;
}

// ---------------- launcher ----------------
extern "C" void kernel_launch(void* const* d_in, const int* in_sizes, int n_in,
                              void* d_out, int out_size){
    const float* cls  = (const float*)d_in[0];
    const float* pred = (const float*)d_in[1];
    const float* info = (const float*)d_in[2];
    float* out = (float*)d_out;

    const int DYN = CAP*8 + PRE*16;   // 65536 + 96000 = 161536
    cudaFuncSetAttribute(k_sortnms, cudaFuncAttributeMaxDynamicSharedMemorySize, DYN);

    k_hist<<<dim3(18, BB), 1024>>>(cls);
    k_thresh<<<BB, 1024>>>();
    k_compact<<<dim3(9, BB), 1024>>>(cls, pred, info);
    k_sortnms<<<BB, 1024, DYN>>>(pred, info, out);
}